// round 2
// baseline (speedup 1.0000x reference)
#include <cuda_runtime.h>
#include <math.h>
#include <stdint.h>

#define Hh   12
#define Nn   768
#define C1d  384
#define C2d  128
#define SQKd 16
#define SVd  16
#define PQKd 4
#define PVd  8
#define NCd  384
#define PROJ_DIM 1152   // 192 + 384 + 144 + 432
#define FA_DIM   2112   // 192 + 96*3 + 96 + 1536

#define SCALAR_W 0.14433756729740643f   // sqrt(1/(3*16))
#define POINT_W  0.13608276348795434f   // sqrt(1/(3*18))
#define W2D      0.5773502691896258f    // sqrt(1/3)

// ---------------- scratch (device globals, no allocation) ----------------
__device__ float d_wcat[PROJ_DIM * C1d];
__device__ float d_bcat[PROJ_DIM];
__device__ float d_proj[Nn * PROJ_DIM];
__device__ float d_qs[Nn * Hh * SQKd];
__device__ float d_ks[Nn * Hh * SQKd];
__device__ float d_vs[Nn * Hh * SVd];
__device__ float d_qp[Nn * Hh * PQKd * 3];
__device__ float d_kp[Nn * Hh * PQKd * 3];
__device__ float d_vp[Nn * Hh * PVd * 3];
__device__ float d_qn[Nn * Hh];
__device__ float d_kn[Nn * Hh];
__device__ float d_fa[Nn * FA_DIM];

// ---------------- kernel 0: concat projection weights/biases ----------------
__global__ void concat_w_kernel(const float* __restrict__ wqs, const float* __restrict__ wkvs,
                                const float* __restrict__ wqp, const float* __restrict__ wkvp,
                                const float* __restrict__ bqs, const float* __restrict__ bkvs,
                                const float* __restrict__ bqp, const float* __restrict__ bkvp) {
    int idx = blockIdx.x * blockDim.x + threadIdx.x;
    int stride = gridDim.x * blockDim.x;
    // biases
    for (int o = idx; o < PROJ_DIM; o += stride) {
        float v;
        if (o < 192)      v = bqs[o];
        else if (o < 576) v = bkvs[o - 192];
        else if (o < 720) v = bqp[o - 576];
        else              v = bkvp[o - 720];
        d_bcat[o] = v;
    }
    const int total = PROJ_DIM * C1d;
    for (int t = idx; t < total; t += stride) {
        int o = t / C1d, k = t % C1d;
        float v;
        if (o < 192)      v = wqs[o * C1d + k];
        else if (o < 576) v = wkvs[(o - 192) * C1d + k];
        else if (o < 720) v = wqp[(o - 576) * C1d + k];
        else              v = wkvp[(o - 720) * C1d + k];
        d_wcat[t] = v;
    }
}

// ---------------- generic tiled fp32 GEMM: C[M,O] = X[M,K] @ W[O,K]^T + bias ----------------
// Requires M%64==0, O%64==0, K%16==0.
__global__ void gemm_tn_kernel(const float* __restrict__ X, const float* __restrict__ W,
                               const float* __restrict__ bias, float* __restrict__ C,
                               int M, int K, int O) {
    __shared__ float xs[64][17];
    __shared__ float wsh[64][17];
    const int m0 = blockIdx.y * 64;
    const int o0 = blockIdx.x * 64;
    const int tx = threadIdx.x;
    const int tm = (tx & 15) * 4;
    const int to = (tx >> 4) * 4;
    float acc[4][4] = {};
    for (int k0 = 0; k0 < K; k0 += 16) {
        for (int idx = tx; idx < 64 * 16; idx += 256) {
            int r = idx >> 4, c = idx & 15;
            xs[r][c]  = X[(size_t)(m0 + r) * K + k0 + c];
            wsh[r][c] = W[(size_t)(o0 + r) * K + k0 + c];
        }
        __syncthreads();
#pragma unroll
        for (int k = 0; k < 16; k++) {
            float a[4], b[4];
#pragma unroll
            for (int i = 0; i < 4; i++) { a[i] = xs[tm + i][k]; b[i] = wsh[to + i][k]; }
#pragma unroll
            for (int i = 0; i < 4; i++)
#pragma unroll
                for (int j = 0; j < 4; j++) acc[i][j] += a[i] * b[j];
        }
        __syncthreads();
    }
#pragma unroll
    for (int i = 0; i < 4; i++)
#pragma unroll
        for (int j = 0; j < 4; j++)
            C[(size_t)(m0 + tm + i) * O + o0 + to + j] = acc[i][j] + bias[o0 + to + j];
}

// ---------------- kernel 2: rotations, point frames, qn/kn ----------------
__global__ void rot_kernel(const float* __restrict__ rot, const float* __restrict__ trans) {
    const int n = blockIdx.x;
    const int tid = threadIdx.x;  // 192 threads
    __shared__ float R[9], t3[3], qn_s[Hh], kn_s[Hh];
    const float* pr = d_proj + (size_t)n * PROJ_DIM;
    if (tid < 9)  R[tid] = rot[n * 9 + tid];
    if (tid < 3)  t3[tid] = trans[n * 3 + tid];
    if (tid < Hh) { qn_s[tid] = 0.f; kn_s[tid] = 0.f; }
    __syncthreads();

    // q_scalar copy
    {
        int o = tid;  // 192 threads == 192 elems
        d_qs[n * 192 + o] = pr[o];
    }
    // kv_scalar split
    for (int o = tid; o < 384; o += 192) {
        int h = o >> 5, d = o & 31;
        float v = pr[192 + o];
        if (d < 16) d_ks[n * 192 + h * 16 + d] = v;
        else        d_vs[n * 192 + h * 16 + (d - 16)] = v;
    }
    // q points: m in [0,48)
    if (tid < 48) {
        int m = tid;
        float p0 = pr[576 + 0 * 48 + m];
        float p1 = pr[576 + 1 * 48 + m];
        float p2 = pr[576 + 2 * 48 + m];
        float g0 = R[0] * p0 + R[1] * p1 + R[2] * p2 + t3[0];
        float g1 = R[3] * p0 + R[4] * p1 + R[5] * p2 + t3[1];
        float g2 = R[6] * p0 + R[7] * p1 + R[8] * p2 + t3[2];
        int h = m >> 2, p = m & 3;
        int base = n * 144 + h * 12 + p * 3;
        d_qp[base + 0] = g0; d_qp[base + 1] = g1; d_qp[base + 2] = g2;
        atomicAdd(&qn_s[h], g0 * g0 + g1 * g1 + g2 * g2);
    } else {
        // kv points: m in [0,144)
        int m = tid - 48;
        float p0 = pr[720 + 0 * 144 + m];
        float p1 = pr[720 + 1 * 144 + m];
        float p2 = pr[720 + 2 * 144 + m];
        float g0 = R[0] * p0 + R[1] * p1 + R[2] * p2 + t3[0];
        float g1 = R[3] * p0 + R[4] * p1 + R[5] * p2 + t3[1];
        float g2 = R[6] * p0 + R[7] * p1 + R[8] * p2 + t3[2];
        int h = m / 12, pp = m % 12;
        if (pp < 4) {
            int base = n * 144 + h * 12 + pp * 3;
            d_kp[base + 0] = g0; d_kp[base + 1] = g1; d_kp[base + 2] = g2;
            atomicAdd(&kn_s[h], g0 * g0 + g1 * g1 + g2 * g2);
        } else {
            int base = n * 288 + h * 24 + (pp - 4) * 3;
            d_vp[base + 0] = g0; d_vp[base + 1] = g1; d_vp[base + 2] = g2;
        }
    }
    __syncthreads();
    if (tid < Hh) { d_qn[n * Hh + tid] = qn_s[tid]; d_kn[n * Hh + tid] = kn_s[tid]; }
}

// ---------------- kernel 3: fused logits + softmax + weighted sums (per residue i) ----------------
// 768 blocks, 384 threads, ~63 KB dynamic smem.
__global__ void attn_kernel(const float* __restrict__ in2d,
                            const float* __restrict__ w_a2, const float* __restrict__ b_a2,
                            const float* __restrict__ mask, const float* __restrict__ tpw,
                            const float* __restrict__ rot, const float* __restrict__ trans) {
    extern __shared__ float sm[];
    float* lg   = sm;             // 12*768
    float* xs   = lg + 9216;      // 32*129
    float* ws   = xs + 4128;      // 12*128
    float* qsi  = ws + 1536;      // 192
    float* qpi  = qsi + 192;      // 144
    float* qni  = qpi + 144;      // 12
    float* pwb  = qni + 12;       // 12
    float* b2s  = pwb + 12;       // 12
    float* rpg  = b2s + 12;       // 288
    float* loc  = rpg + 288;      // 288
    float* Ri   = loc + 288;      // 9
    float* ti   = Ri + 9;         // 3   (total 15840 floats)

    const int i   = blockIdx.x;
    const int tid = threadIdx.x;  // 384
    const int h   = tid >> 5;     // warp id == head, 0..11
    const int jl  = tid & 31;

    for (int o = tid; o < 1536; o += 384) ws[o] = w_a2[o];
    if (tid < 192) qsi[tid] = d_qs[i * 192 + tid];
    if (tid < 144) qpi[tid] = d_qp[i * 144 + tid];
    if (tid < 12) {
        qni[tid] = d_qn[i * 12 + tid];
        float x = tpw[tid];
        float sp = (x > 20.f) ? x : log1pf(__expf(x));
        pwb[tid] = -0.5f * sp * POINT_W;
        b2s[tid] = W2D * b_a2[tid];
    }
    if (tid < 9) Ri[tid] = rot[i * 9 + tid];
    if (tid < 3) ti[tid] = trans[i * 3 + tid];
    const float mi = mask[i];
    __syncthreads();

    // ---- pass 1: logits ----
    for (int jt = 0; jt < Nn; jt += 32) {
        for (int idx = tid; idx < 4096; idx += 384) {
            int r = idx >> 7, c = idx & 127;
            xs[r * 129 + c] = in2d[((size_t)i * Nn + jt + r) * C2d + c];
        }
        __syncthreads();
        const int j = jt + jl;
        const float* xrow = &xs[jl * 129];
        const float* wrow = &ws[h * 128];
        float acc = 0.f;
#pragma unroll 8
        for (int c = 0; c < 128; c++) acc += xrow[c] * wrow[c];
        acc = W2D * acc + b2s[h];

        float s = 0.f;
        const float* kr = d_ks + (size_t)j * 192 + h * 16;
        const float* qr = qsi + h * 16;
#pragma unroll
        for (int d = 0; d < 16; d++) s += qr[d] * kr[d];
        acc += SCALAR_W * s;

        float qk = 0.f;
        const float* kpp = d_kp + (size_t)j * 144 + h * 12;
        const float* qpp = qpi + h * 12;
#pragma unroll
        for (int d = 0; d < 12; d++) qk += qpp[d] * kpp[d];
        acc += pwb[h] * (qni[h] + d_kn[j * 12 + h] - 2.f * qk);

        acc -= 100000.f * (1.f - mi * mask[j]);
        lg[h * Nn + j] = acc;
        __syncthreads();
    }

    // ---- softmax: one warp per head ----
    {
        float* row = lg + h * Nn;
        float mx = -1e30f;
        for (int k = jl; k < Nn; k += 32) mx = fmaxf(mx, row[k]);
#pragma unroll
        for (int off = 16; off > 0; off >>= 1) mx = fmaxf(mx, __shfl_xor_sync(0xffffffffu, mx, off));
        float sum = 0.f;
        for (int k = jl; k < Nn; k += 32) { float e = __expf(row[k] - mx); row[k] = e; sum += e; }
#pragma unroll
        for (int off = 16; off > 0; off >>= 1) sum += __shfl_xor_sync(0xffffffffu, sum, off);
        float inv = 1.f / sum;
        for (int k = jl; k < Nn; k += 32) row[k] *= inv;
    }
    __syncthreads();

    float* fa = d_fa + (size_t)i * FA_DIM;

    // ---- pass 2a: r2d = attn @ inputs_2d[i]   (thread: c = tid%128, heads {g, g+3, g+6, g+9}) ----
    {
        const int cc = tid & 127;
        const int g  = tid >> 7;  // 0..2
        float a4[4] = {0.f, 0.f, 0.f, 0.f};
        for (int jt = 0; jt < Nn; jt += 32) {
            for (int idx = tid; idx < 4096; idx += 384) {
                int r = idx >> 7, c = idx & 127;
                xs[r * 129 + c] = in2d[((size_t)i * Nn + jt + r) * C2d + c];
            }
            __syncthreads();
#pragma unroll 4
            for (int r = 0; r < 32; r++) {
                float x = xs[r * 129 + cc];
#pragma unroll
                for (int u = 0; u < 4; u++)
                    a4[u] += lg[(g + u * 3) * Nn + jt + r] * x;
            }
            __syncthreads();
        }
#pragma unroll
        for (int u = 0; u < 4; u++) fa[576 + (g + u * 3) * 128 + cc] = a4[u];
    }

    // ---- pass 2b: result_scalar (192) and rpg (288) ----
    for (int oo = tid; oo < 480; oo += 384) {
        if (oo < 192) {
            const int hh = oo >> 4;
            const float* row = lg + hh * Nn;
            float a = 0.f;
#pragma unroll 4
            for (int j = 0; j < Nn; j++) a += row[j] * d_vs[(size_t)j * 192 + oo];
            fa[oo] = a;
        } else {
            const int o = oo - 192;
            const int hh = o / 24;
            const float* row = lg + hh * Nn;
            float a = 0.f;
#pragma unroll 4
            for (int j = 0; j < Nn; j++) a += row[j] * d_vp[(size_t)j * 288 + o];
            rpg[o] = a;
        }
    }
    __syncthreads();

    // ---- local frame + dist ----
    if (tid < 288) {
        const int idim = tid / 96, m = tid % 96;
        const int hh = m >> 3, p = m & 7;
        const int base = hh * 24 + p * 3;
        float v0 = rpg[base + 0] - ti[0];
        float v1 = rpg[base + 1] - ti[1];
        float v2 = rpg[base + 2] - ti[2];
        // local = R^T * v :  R[c][idim]
        float l = Ri[0 * 3 + idim] * v0 + Ri[1 * 3 + idim] * v1 + Ri[2 * 3 + idim] * v2;
        loc[idim * 96 + m] = l;
        fa[192 + idim * 96 + m] = l;
    }
    __syncthreads();
    if (tid < 96) {
        float l0 = loc[tid], l1 = loc[96 + tid], l2 = loc[192 + tid];
        fa[480 + tid] = sqrtf(1e-8f + l0 * l0 + l1 * l1 + l2 * l2);
    }
}

// ---------------- launch ----------------
extern "C" void kernel_launch(void* const* d_in, const int* in_sizes, int n_in,
                              void* d_out, int out_size) {
    const float* inputs_1d = (const float*)d_in[0];
    const float* inputs_2d = (const float*)d_in[1];
    const float* mask      = (const float*)d_in[2];
    const float* rotation  = (const float*)d_in[3];
    const float* translat  = (const float*)d_in[4];
    const float* w_qs      = (const float*)d_in[5];
    const float* b_qs      = (const float*)d_in[6];
    const float* w_kvs     = (const float*)d_in[7];
    const float* b_kvs     = (const float*)d_in[8];
    const float* w_qp      = (const float*)d_in[9];
    const float* b_qp      = (const float*)d_in[10];
    const float* w_kvp     = (const float*)d_in[11];
    const float* b_kvp     = (const float*)d_in[12];
    const float* tpw       = (const float*)d_in[13];
    const float* w_a2      = (const float*)d_in[14];
    const float* b_a2      = (const float*)d_in[15];
    const float* w_out     = (const float*)d_in[16];
    const float* b_out     = (const float*)d_in[17];
    float* out = (float*)d_out;

    void *p_wcat, *p_bcat, *p_proj, *p_fa;
    cudaGetSymbolAddress(&p_wcat, d_wcat);
    cudaGetSymbolAddress(&p_bcat, d_bcat);
    cudaGetSymbolAddress(&p_proj, d_proj);
    cudaGetSymbolAddress(&p_fa,   d_fa);

    // 0) concat projection weights
    concat_w_kernel<<<256, 256>>>(w_qs, w_kvs, w_qp, w_kvp, b_qs, b_kvs, b_qp, b_kvp);

    // 1) projections: [768 x 384] @ [1152 x 384]^T
    {
        dim3 grid(PROJ_DIM / 64, Nn / 64);
        gemm_tn_kernel<<<grid, 256>>>(inputs_1d, (const float*)p_wcat, (const float*)p_bcat,
                                      (float*)p_proj, Nn, C1d, PROJ_DIM);
    }

    // 2) rotations / point frames / norms
    rot_kernel<<<Nn, 192>>>(rotation, translat);

    // 3) fused attention per residue
    {
        const int smem_bytes = 15840 * (int)sizeof(float);
        cudaFuncSetAttribute(attn_kernel, cudaFuncAttributeMaxDynamicSharedMemorySize, smem_bytes);
        attn_kernel<<<Nn, 384, smem_bytes>>>(inputs_2d, w_a2, b_a2, mask, tpw, rotation, translat);
    }

    // 4) output projection: [768 x 2112] @ [384 x 2112]^T
    {
        dim3 grid(NCd / 64, Nn / 64);
        gemm_tn_kernel<<<grid, 256>>>((const float*)p_fa, w_out, b_out, out, Nn, FA_DIM, NCd);
    }
}

// round 3
// speedup vs baseline: 2.1872x; 2.1872x over previous
#include <cuda_runtime.h>
#include <math.h>
#include <stdint.h>

#define Hh   12
#define Nn   768
#define C1d  384
#define C2d  128
#define PROJ_DIM 1152
#define FA_DIM   2112

#define SCALAR_W 0.14433756729740643f
#define POINT_W  0.13608276348795434f
#define W2D      0.5773502691896258f

// ---------------- scratch ----------------
__device__ float d_wcat[PROJ_DIM * C1d];
__device__ float d_bcat[PROJ_DIM];
__device__ float d_proj[Nn * PROJ_DIM];
__device__ float d_qs[Nn * 192];
__device__ float d_qp[Nn * 144];
__device__ float d_qn[Nn * Hh];
__device__ float d_kT[Hh * 29 * Nn];      // [h][f][j]: f<16 ks, 16..27 kp, 28 kn
__device__ float d_vcat[Nn * 480];        // [j][480]: 192 vs (h*16+d), 288 vp (h*24+p*3+c)
__device__ float d_lg[Hh * Nn * Nn];      // [(i*12+h)][j]
__device__ float d_attn[Hh * Nn * Nn];    // row-major [(i*12+h)][j]
__device__ float d_attnT[Nn * Nn * Hh];   // [(i*768+j)][h]
__device__ float d_rpg[Nn * 288];
__device__ float d_fa[Nn * FA_DIM];
__device__ float d_part[4 * Nn * 384];

// ---------------- K0: concat proj weights ----------------
__global__ void concat_w_kernel(const float* __restrict__ wqs, const float* __restrict__ wkvs,
                                const float* __restrict__ wqp, const float* __restrict__ wkvp,
                                const float* __restrict__ bqs, const float* __restrict__ bkvs,
                                const float* __restrict__ bqp, const float* __restrict__ bkvp) {
    int idx = blockIdx.x * blockDim.x + threadIdx.x;
    int stride = gridDim.x * blockDim.x;
    for (int o = idx; o < PROJ_DIM; o += stride) {
        float v;
        if (o < 192)      v = bqs[o];
        else if (o < 576) v = bkvs[o - 192];
        else if (o < 720) v = bqp[o - 576];
        else              v = bkvp[o - 720];
        d_bcat[o] = v;
    }
    const int total = PROJ_DIM * C1d;
    for (int t = idx; t < total; t += stride) {
        int o = t / C1d, k = t % C1d;
        float v;
        if (o < 192)      v = wqs[o * C1d + k];
        else if (o < 576) v = wkvs[(o - 192) * C1d + k];
        else if (o < 720) v = wqp[(o - 576) * C1d + k];
        else              v = wkvp[(o - 720) * C1d + k];
        d_wcat[t] = v;
    }
}

// ---------------- generic fp32 GEMM: C[M,O] = X[M,:]@W[O,:]^T (+bias) ----------------
__global__ void gemm_tn2(const float* __restrict__ X, int ldx,
                         const float* __restrict__ W, int ldw,
                         const float* __restrict__ bias, float* __restrict__ C,
                         int Klen, int O) {
    __shared__ float xs[64][17];
    __shared__ float wsh[64][17];
    const int m0 = blockIdx.y * 64;
    const int o0 = blockIdx.x * 64;
    const int tx = threadIdx.x;
    const int tm = (tx & 15) * 4;
    const int to = (tx >> 4) * 4;
    float acc[4][4] = {};
    for (int k0 = 0; k0 < Klen; k0 += 16) {
        for (int idx = tx; idx < 64 * 16; idx += 256) {
            int r = idx >> 4, c = idx & 15;
            xs[r][c]  = X[(size_t)(m0 + r) * ldx + k0 + c];
            wsh[r][c] = W[(size_t)(o0 + r) * ldw + k0 + c];
        }
        __syncthreads();
#pragma unroll
        for (int k = 0; k < 16; k++) {
            float a[4], b[4];
#pragma unroll
            for (int i = 0; i < 4; i++) { a[i] = xs[tm + i][k]; b[i] = wsh[to + i][k]; }
#pragma unroll
            for (int i = 0; i < 4; i++)
#pragma unroll
                for (int j = 0; j < 4; j++) acc[i][j] += a[i] * b[j];
        }
        __syncthreads();
    }
#pragma unroll
    for (int i = 0; i < 4; i++)
#pragma unroll
        for (int j = 0; j < 4; j++) {
            float b = bias ? bias[o0 + to + j] : 0.f;
            C[(size_t)(m0 + tm + i) * O + o0 + to + j] = acc[i][j] + b;
        }
}

// ---------------- K2: rotations / frames / norms / layout builders ----------------
__global__ void rot_kernel(const float* __restrict__ rot, const float* __restrict__ trans) {
    const int n = blockIdx.x;
    const int tid = threadIdx.x;  // 192
    __shared__ float R[9], t3[3], qn_s[Hh], kn_s[Hh];
    const float* pr = d_proj + (size_t)n * PROJ_DIM;
    if (tid < 9)  R[tid] = rot[n * 9 + tid];
    if (tid < 3)  t3[tid] = trans[n * 3 + tid];
    if (tid < Hh) { qn_s[tid] = 0.f; kn_s[tid] = 0.f; }
    __syncthreads();

    d_qs[n * 192 + tid] = pr[tid];
    for (int o = tid; o < 384; o += 192) {
        int h = o >> 5, d = o & 31;
        float v = pr[192 + o];
        if (d < 16) d_kT[(size_t)(h * 29 + d) * Nn + n] = v;
        else        d_vcat[(size_t)n * 480 + h * 16 + (d - 16)] = v;
    }
    if (tid < 48) {
        int m = tid;
        float p0 = pr[576 + 0 * 48 + m];
        float p1 = pr[576 + 1 * 48 + m];
        float p2 = pr[576 + 2 * 48 + m];
        float g0 = R[0] * p0 + R[1] * p1 + R[2] * p2 + t3[0];
        float g1 = R[3] * p0 + R[4] * p1 + R[5] * p2 + t3[1];
        float g2 = R[6] * p0 + R[7] * p1 + R[8] * p2 + t3[2];
        int h = m >> 2, p = m & 3;
        int base = n * 144 + h * 12 + p * 3;
        d_qp[base + 0] = g0; d_qp[base + 1] = g1; d_qp[base + 2] = g2;
        atomicAdd(&qn_s[h], g0 * g0 + g1 * g1 + g2 * g2);
    } else {
        int m = tid - 48;
        float p0 = pr[720 + 0 * 144 + m];
        float p1 = pr[720 + 1 * 144 + m];
        float p2 = pr[720 + 2 * 144 + m];
        float g0 = R[0] * p0 + R[1] * p1 + R[2] * p2 + t3[0];
        float g1 = R[3] * p0 + R[4] * p1 + R[5] * p2 + t3[1];
        float g2 = R[6] * p0 + R[7] * p1 + R[8] * p2 + t3[2];
        int h = m / 12, pp = m % 12;
        if (pp < 4) {
            int fb = h * 29 + 16 + pp * 3;
            d_kT[(size_t)(fb + 0) * Nn + n] = g0;
            d_kT[(size_t)(fb + 1) * Nn + n] = g1;
            d_kT[(size_t)(fb + 2) * Nn + n] = g2;
            atomicAdd(&kn_s[h], g0 * g0 + g1 * g1 + g2 * g2);
        } else {
            int base = n * 480 + 192 + h * 24 + (pp - 4) * 3;
            d_vcat[base + 0] = g0; d_vcat[base + 1] = g1; d_vcat[base + 2] = g2;
        }
    }
    __syncthreads();
    if (tid < Hh) {
        d_qn[n * Hh + tid] = qn_s[tid];
        d_kT[(size_t)(tid * 29 + 28) * Nn + n] = kn_s[tid];
    }
}

// ---------------- K3: logits = a2d GEMM + scalar/point epilogue + mask ----------------
// grid (6, 768), 128 threads, dyn smem 75408 B
__global__ __launch_bounds__(128) void logits_kernel(
        const float* __restrict__ in2d, const float* __restrict__ w_a2,
        const float* __restrict__ b_a2, const float* __restrict__ mask,
        const float* __restrict__ tpw) {
    extern __shared__ float sm[];
    float4* xs4 = (float4*)sm;                 // 128*33 float4
    float4* ws4 = (float4*)(sm + 16896);       // 12*33 float4
    float* qss = sm + 16896 + 1584;            // 192
    float* qps = qss + 192;                    // 144
    float* qns = qps + 144;                    // 12
    float* pwb = qns + 12;                     // 12
    float* b2s = pwb + 12;                     // 12

    const int i = blockIdx.y;
    const int j0 = blockIdx.x * 128;
    const int tid = threadIdx.x;

    const float4* in4 = (const float4*)in2d + ((size_t)i * Nn + j0) * 32;
#pragma unroll
    for (int t = 0; t < 32; t++) {
        int f = tid + 128 * t;
        xs4[(f >> 5) * 33 + (f & 31)] = in4[f];
    }
    const float4* w4 = (const float4*)w_a2;
#pragma unroll
    for (int t = 0; t < 3; t++) {
        int f = tid + 128 * t;
        ws4[(f >> 5) * 33 + (f & 31)] = w4[f];
    }
    for (int t = tid; t < 192; t += 128) qss[t] = d_qs[i * 192 + t];
    for (int t = tid; t < 144; t += 128) qps[t] = d_qp[i * 144 + t];
    if (tid < 12) {
        qns[tid] = d_qn[i * Hh + tid];
        float x = tpw[tid];
        float sp = (x > 20.f) ? x : log1pf(__expf(x));
        pwb[tid] = -0.5f * sp * POINT_W;
        b2s[tid] = W2D * b_a2[tid];
    }
    __syncthreads();

    float acc[12] = {};
#pragma unroll
    for (int c4 = 0; c4 < 32; c4++) {
        float4 x = xs4[tid * 33 + c4];
#pragma unroll
        for (int h = 0; h < 12; h++) {
            float4 w = ws4[h * 33 + c4];
            acc[h] += x.x * w.x + x.y * w.y + x.z * w.z + x.w * w.w;
        }
    }

    const int j = j0 + tid;
    const float mterm = -100000.f * (1.f - mask[i] * mask[j]);
    const float* kTj = d_kT + j;
    for (int h = 0; h < 12; h++) {
        const float* kb = kTj + (size_t)(h * 29) * Nn;
        float s = 0.f, qk = 0.f;
#pragma unroll
        for (int d = 0; d < 16; d++) s += qss[h * 16 + d] * kb[(size_t)d * Nn];
#pragma unroll
        for (int e = 0; e < 12; e++) qk += qps[h * 12 + e] * kb[(size_t)(16 + e) * Nn];
        float kn = kb[(size_t)28 * Nn];
        float lgv = acc[h] * W2D + b2s[h] + SCALAR_W * s
                  + pwb[h] * (qns[h] + kn - 2.f * qk) + mterm;
        d_lg[((size_t)i * 12 + h) * Nn + j] = lgv;
    }
}

// ---------------- K4: softmax, writes attn (row-major) + attnT ----------------
__global__ void softmax_kernel() {
    __shared__ float att_s[Nn * Hh];
    const int i = blockIdx.x;
    const int tid = threadIdx.x;  // 384
    const int h = tid >> 5, jl = tid & 31;

    const float4* row4 = (const float4*)(d_lg + ((size_t)i * 12 + h) * Nn);
    float4 v[6];
    float mx = -1e30f;
#pragma unroll
    for (int k = 0; k < 6; k++) {
        v[k] = row4[jl + k * 32];
        mx = fmaxf(mx, fmaxf(fmaxf(v[k].x, v[k].y), fmaxf(v[k].z, v[k].w)));
    }
#pragma unroll
    for (int off = 16; off > 0; off >>= 1) mx = fmaxf(mx, __shfl_xor_sync(0xffffffffu, mx, off));
    float sum = 0.f;
#pragma unroll
    for (int k = 0; k < 6; k++) {
        v[k].x = __expf(v[k].x - mx); v[k].y = __expf(v[k].y - mx);
        v[k].z = __expf(v[k].z - mx); v[k].w = __expf(v[k].w - mx);
        sum += v[k].x + v[k].y + v[k].z + v[k].w;
    }
#pragma unroll
    for (int off = 16; off > 0; off >>= 1) sum += __shfl_xor_sync(0xffffffffu, sum, off);
    const float inv = 1.f / sum;

    float4* outr = (float4*)(d_attn + ((size_t)i * 12 + h) * Nn);
#pragma unroll
    for (int k = 0; k < 6; k++) {
        float4 s4;
        s4.x = v[k].x * inv; s4.y = v[k].y * inv; s4.z = v[k].z * inv; s4.w = v[k].w * inv;
        outr[jl + k * 32] = s4;
        int jb = (jl + 32 * k) * 4;
        att_s[(jb + 0) * 12 + h] = s4.x;
        att_s[(jb + 1) * 12 + h] = s4.y;
        att_s[(jb + 2) * 12 + h] = s4.z;
        att_s[(jb + 3) * 12 + h] = s4.w;
    }
    __syncthreads();
    const float4* at4 = (const float4*)att_s;
    float4* ot4 = (float4*)(d_attnT + (size_t)i * (Nn * Hh));
#pragma unroll
    for (int k = 0; k < 6; k++) {
        int f = tid + 384 * k;
        ot4[f] = at4[f];
    }
}

// ---------------- K5: r2d per-i GEMM attn[12,768] @ X[768,128] ----------------
// 768 blocks, 128 threads, dyn smem 61440 B
__global__ __launch_bounds__(128) void r2d_kernel(const float* __restrict__ in2d) {
    extern __shared__ float sm[];
    float* att_s = sm;            // 9216
    float* red   = sm + 9216;     // 6144
    const int i = blockIdx.x;
    const int tid = threadIdx.x;

    float4* as4 = (float4*)att_s;
    const float4* at4 = (const float4*)(d_attnT + (size_t)i * (Nn * Hh));
#pragma unroll
    for (int k = 0; k < 18; k++) { int f = tid + 128 * k; as4[f] = at4[f]; }
    __syncthreads();

    const int c4 = tid & 31, js = tid >> 5;
    float acc[48] = {};
    const float4* x4p = (const float4*)in2d + (size_t)i * Nn * 32 + c4;
    const int jend = js * 192 + 192;
    for (int j = js * 192; j < jend; j++) {
        float4 x = x4p[(size_t)j * 32];
        float4 a0 = as4[j * 3 + 0], a1 = as4[j * 3 + 1], a2 = as4[j * 3 + 2];
        float a[12] = {a0.x, a0.y, a0.z, a0.w, a1.x, a1.y, a1.z, a1.w, a2.x, a2.y, a2.z, a2.w};
#pragma unroll
        for (int h = 0; h < 12; h++) {
            acc[h * 4 + 0] += a[h] * x.x;
            acc[h * 4 + 1] += a[h] * x.y;
            acc[h * 4 + 2] += a[h] * x.z;
            acc[h * 4 + 3] += a[h] * x.w;
        }
    }
#pragma unroll
    for (int k = 0; k < 48; k++) {
        int h = k >> 2, u = k & 3;
        red[js * 1536 + h * 128 + c4 * 4 + u] = acc[k];
    }
    __syncthreads();
    float* fa = d_fa + (size_t)i * FA_DIM + 576;
#pragma unroll
    for (int k = 0; k < 12; k++) {
        int o = tid + 128 * k;
        fa[o] = red[o] + red[1536 + o] + red[3072 + o] + red[4608 + o];
    }
}

// ---------------- K6: PV tiled GEMM (result_scalar + rpg) ----------------
// grid (12 i-tiles, 12 h), 256 threads
__global__ void pv_kernel() {
    __shared__ float att_s[64 * 33];
    __shared__ float v_s[32 * 40];
    const int i0 = blockIdx.x * 64;
    const int h = blockIdx.y;
    const int tid = threadIdx.x;
    const int io2 = tid & 31, ov = tid >> 5;  // ov 0..7
    float acc0[5] = {}, acc1[5] = {};

    for (int jt = 0; jt < Nn; jt += 32) {
        __syncthreads();
#pragma unroll
        for (int k = 0; k < 8; k++) {
            int f = tid + 256 * k;
            int il = f >> 5, jl = f & 31;
            att_s[il * 33 + jl] = d_attn[((size_t)(i0 + il) * 12 + h) * Nn + jt + jl];
        }
#pragma unroll
        for (int k = 0; k < 5; k++) {
            int f = tid + 256 * k;
            int jl = f / 40, o = f % 40;
            const float* vr = d_vcat + (size_t)(jt + jl) * 480;
            v_s[jl * 40 + o] = (o < 16) ? vr[h * 16 + o] : vr[192 + h * 24 + (o - 16)];
        }
        __syncthreads();
#pragma unroll 4
        for (int jl = 0; jl < 32; jl++) {
            float a0 = att_s[io2 * 33 + jl];
            float a1 = att_s[(io2 + 32) * 33 + jl];
#pragma unroll
            for (int u = 0; u < 5; u++) {
                float vv = v_s[jl * 40 + ov * 5 + u];
                acc0[u] += a0 * vv;
                acc1[u] += a1 * vv;
            }
        }
    }
#pragma unroll
    for (int u = 0; u < 5; u++) {
        int o = ov * 5 + u;
        int i_a = i0 + io2, i_b = i0 + io2 + 32;
        if (o < 16) {
            d_fa[(size_t)i_a * FA_DIM + h * 16 + o] = acc0[u];
            d_fa[(size_t)i_b * FA_DIM + h * 16 + o] = acc1[u];
        } else {
            d_rpg[i_a * 288 + h * 24 + (o - 16)] = acc0[u];
            d_rpg[i_b * 288 + h * 24 + (o - 16)] = acc1[u];
        }
    }
}

// ---------------- K7: local frame + dist ----------------
__global__ void local_kernel(const float* __restrict__ rot, const float* __restrict__ trans) {
    __shared__ float rpg_s[288], loc[288], Ri[9], ti[3];
    const int i = blockIdx.x;
    const int tid = threadIdx.x;  // 288
    rpg_s[tid] = d_rpg[i * 288 + tid];
    if (tid < 9) Ri[tid] = rot[i * 9 + tid];
    if (tid < 3) ti[tid] = trans[i * 3 + tid];
    __syncthreads();
    float* fa = d_fa + (size_t)i * FA_DIM;
    const int idim = tid / 96, m = tid % 96;
    const int hh = m >> 3, p = m & 7;
    const int base = hh * 24 + p * 3;
    float v0 = rpg_s[base + 0] - ti[0];
    float v1 = rpg_s[base + 1] - ti[1];
    float v2 = rpg_s[base + 2] - ti[2];
    float l = Ri[idim] * v0 + Ri[3 + idim] * v1 + Ri[6 + idim] * v2;
    loc[idim * 96 + m] = l;
    fa[192 + idim * 96 + m] = l;
    __syncthreads();
    if (tid < 96) {
        float l0 = loc[tid], l1 = loc[96 + tid], l2 = loc[192 + tid];
        fa[480 + tid] = sqrtf(1e-8f + l0 * l0 + l1 * l1 + l2 * l2);
    }
}

// ---------------- K8b: reduce out partials + bias ----------------
__global__ void reduce_out_kernel(const float* __restrict__ b_out, float* __restrict__ out) {
    const int idx = blockIdx.x * 256 + threadIdx.x;
    const int total = Nn * 384;
    if (idx < total) {
        out[idx] = b_out[idx % 384] + d_part[idx] + d_part[total + idx]
                 + d_part[2 * total + idx] + d_part[3 * total + idx];
    }
}

// ---------------- launch ----------------
extern "C" void kernel_launch(void* const* d_in, const int* in_sizes, int n_in,
                              void* d_out, int out_size) {
    const float* inputs_1d = (const float*)d_in[0];
    const float* inputs_2d = (const float*)d_in[1];
    const float* mask      = (const float*)d_in[2];
    const float* rotation  = (const float*)d_in[3];
    const float* translat  = (const float*)d_in[4];
    const float* w_qs      = (const float*)d_in[5];
    const float* b_qs      = (const float*)d_in[6];
    const float* w_kvs     = (const float*)d_in[7];
    const float* b_kvs     = (const float*)d_in[8];
    const float* w_qp      = (const float*)d_in[9];
    const float* b_qp      = (const float*)d_in[10];
    const float* w_kvp     = (const float*)d_in[11];
    const float* b_kvp     = (const float*)d_in[12];
    const float* tpw       = (const float*)d_in[13];
    const float* w_a2      = (const float*)d_in[14];
    const float* b_a2      = (const float*)d_in[15];
    const float* w_out     = (const float*)d_in[16];
    const float* b_out     = (const float*)d_in[17];
    float* out = (float*)d_out;

    void *p_wcat, *p_bcat, *p_proj, *p_fa, *p_part;
    cudaGetSymbolAddress(&p_wcat, d_wcat);
    cudaGetSymbolAddress(&p_bcat, d_bcat);
    cudaGetSymbolAddress(&p_proj, d_proj);
    cudaGetSymbolAddress(&p_fa,   d_fa);
    cudaGetSymbolAddress(&p_part, d_part);

    concat_w_kernel<<<256, 256>>>(w_qs, w_kvs, w_qp, w_kvp, b_qs, b_kvs, b_qp, b_kvp);

    // projections: [768 x 384] @ [1152 x 384]^T
    {
        dim3 grid(PROJ_DIM / 64, Nn / 64);
        gemm_tn2<<<grid, 256>>>(inputs_1d, C1d, (const float*)p_wcat, C1d,
                                (const float*)p_bcat, (float*)p_proj, C1d, PROJ_DIM);
    }

    rot_kernel<<<Nn, 192>>>(rotation, translat);

    // logits
    {
        const int smem = (16896 + 1584 + 372) * (int)sizeof(float);
        cudaFuncSetAttribute(logits_kernel, cudaFuncAttributeMaxDynamicSharedMemorySize, smem);
        dim3 grid(Nn / 128, Nn);
        logits_kernel<<<grid, 128, smem>>>(inputs_2d, w_a2, b_a2, mask, tpw);
    }

    softmax_kernel<<<Nn, 384>>>();

    // r2d
    {
        const int smem = (9216 + 6144) * (int)sizeof(float);
        cudaFuncSetAttribute(r2d_kernel, cudaFuncAttributeMaxDynamicSharedMemorySize, smem);
        r2d_kernel<<<Nn, 128, smem>>>(inputs_2d);
    }

    pv_kernel<<<dim3(Nn / 64, Hh), 256>>>();
    local_kernel<<<Nn, 288>>>(rotation, translat);

    // out GEMM with 4-way K split
    for (int z = 0; z < 4; z++) {
        dim3 grid(384 / 64, Nn / 64);
        gemm_tn2<<<grid, 256>>>((const float*)p_fa + z * 528, FA_DIM,
                                w_out + z * 528, FA_DIM,
                                nullptr, (float*)p_part + (size_t)z * Nn * 384,
                                528, 384);
    }
    reduce_out_kernel<<<(Nn * 384 + 255) / 256, 256>>>(b_out, out);
}

// round 4
// speedup vs baseline: 3.3754x; 1.5432x over previous
#include <cuda_runtime.h>
#include <math.h>
#include <stdint.h>

#define Hh   12
#define Nn   768
#define C1d  384
#define C2d  128
#define PROJ_DIM 1152
#define FA_DIM   2112

#define SCALAR_W 0.14433756729740643f
#define POINT_W  0.13608276348795434f
#define W2D      0.5773502691896258f

// ---------------- scratch ----------------
__device__ float d_wcat[PROJ_DIM * C1d];
__device__ float d_bcat[PROJ_DIM];
__device__ float d_proj[Nn * PROJ_DIM];
__device__ float d_qcat[Nn * 384];        // [i][h*32+f]: f0-15 SCALAR_W*qs, 16-27 -2*pwb*qp, 28 pwb, 29 c_ih
__device__ float d_kT[Hh * 29 * Nn];      // [h][f][j]: f<16 ks, 16..27 kp, 28 kn
__device__ float d_vcat[Nn * 480];        // [j][480]: 192 vs, 288 vp
__device__ float d_lgsp[Nn * Hh * Nn];    // [i][h][j] scalar+point+bias+mask logits
__device__ float d_attn[Hh * Nn * Nn];    // [i][h][j]
__device__ float d_attnT[Nn * Nn * Hh];   // [i][j][h]
__device__ float d_rpg[Nn * 288];
__device__ float d_fa[Nn * FA_DIM];
__device__ float d_part[4 * Nn * 384];

// ---------------- K0: concat proj weights ----------------
__global__ void concat_w_kernel(const float* __restrict__ wqs, const float* __restrict__ wkvs,
                                const float* __restrict__ wqp, const float* __restrict__ wkvp,
                                const float* __restrict__ bqs, const float* __restrict__ bkvs,
                                const float* __restrict__ bqp, const float* __restrict__ bkvp) {
    int idx = blockIdx.x * blockDim.x + threadIdx.x;
    int stride = gridDim.x * blockDim.x;
    for (int o = idx; o < PROJ_DIM; o += stride) {
        float v;
        if (o < 192)      v = bqs[o];
        else if (o < 576) v = bkvs[o - 192];
        else if (o < 720) v = bqp[o - 576];
        else              v = bkvp[o - 720];
        d_bcat[o] = v;
    }
    const int total = PROJ_DIM * C1d;
    for (int t = idx; t < total; t += stride) {
        int o = t / C1d, k = t % C1d;
        float v;
        if (o < 192)      v = wqs[o * C1d + k];
        else if (o < 576) v = wkvs[(o - 192) * C1d + k];
        else if (o < 720) v = wqp[(o - 576) * C1d + k];
        else              v = wkvp[(o - 720) * C1d + k];
        d_wcat[t] = v;
    }
}

// ---------------- generic fp32 GEMM: C[M,O] = X[M,:]@W[O,:]^T (+bias) ----------------
__global__ void gemm_tn2(const float* __restrict__ X, int ldx,
                         const float* __restrict__ W, int ldw,
                         const float* __restrict__ bias, float* __restrict__ C,
                         int Klen, int O) {
    __shared__ float xs[64][17];
    __shared__ float wsh[64][17];
    const int m0 = blockIdx.y * 64;
    const int o0 = blockIdx.x * 64;
    const int tx = threadIdx.x;
    const int tm = (tx & 15) * 4;
    const int to = (tx >> 4) * 4;
    float acc[4][4] = {};
    for (int k0 = 0; k0 < Klen; k0 += 16) {
        for (int idx = tx; idx < 64 * 16; idx += 256) {
            int r = idx >> 4, c = idx & 15;
            xs[r][c]  = X[(size_t)(m0 + r) * ldx + k0 + c];
            wsh[r][c] = W[(size_t)(o0 + r) * ldw + k0 + c];
        }
        __syncthreads();
#pragma unroll
        for (int k = 0; k < 16; k++) {
            float a[4], b[4];
#pragma unroll
            for (int i = 0; i < 4; i++) { a[i] = xs[tm + i][k]; b[i] = wsh[to + i][k]; }
#pragma unroll
            for (int i = 0; i < 4; i++)
#pragma unroll
                for (int j = 0; j < 4; j++) acc[i][j] += a[i] * b[j];
        }
        __syncthreads();
    }
#pragma unroll
    for (int i = 0; i < 4; i++)
#pragma unroll
        for (int j = 0; j < 4; j++) {
            float b = bias ? bias[o0 + to + j] : 0.f;
            C[(size_t)(m0 + tm + i) * O + o0 + to + j] = acc[i][j] + b;
        }
}

// ---------------- out-GEMM with K-split on blockIdx.z ----------------
__global__ void gemm_out_kernel(const float* __restrict__ Wo) {
    __shared__ float xs[64][17];
    __shared__ float wsh[64][17];
    const int z  = blockIdx.z;
    const float* X = d_fa + z * 528;
    const float* W = Wo + z * 528;
    float* C = d_part + (size_t)z * (Nn * 384);
    const int m0 = blockIdx.y * 64;
    const int o0 = blockIdx.x * 64;
    const int tx = threadIdx.x;
    const int tm = (tx & 15) * 4;
    const int to = (tx >> 4) * 4;
    float acc[4][4] = {};
    for (int k0 = 0; k0 < 528; k0 += 16) {
        for (int idx = tx; idx < 64 * 16; idx += 256) {
            int r = idx >> 4, c = idx & 15;
            xs[r][c]  = X[(size_t)(m0 + r) * FA_DIM + k0 + c];
            wsh[r][c] = W[(size_t)(o0 + r) * FA_DIM + k0 + c];
        }
        __syncthreads();
#pragma unroll
        for (int k = 0; k < 16; k++) {
            float a[4], b[4];
#pragma unroll
            for (int i = 0; i < 4; i++) { a[i] = xs[tm + i][k]; b[i] = wsh[to + i][k]; }
#pragma unroll
            for (int i = 0; i < 4; i++)
#pragma unroll
                for (int j = 0; j < 4; j++) acc[i][j] += a[i] * b[j];
        }
        __syncthreads();
    }
#pragma unroll
    for (int i = 0; i < 4; i++)
#pragma unroll
        for (int j = 0; j < 4; j++)
            C[(size_t)(m0 + tm + i) * 384 + o0 + to + j] = acc[i][j];
}

// ---------------- K2: rotations / frames / norms / packed q ----------------
__global__ void rot_kernel(const float* __restrict__ rot, const float* __restrict__ trans,
                           const float* __restrict__ tpw, const float* __restrict__ b_a2) {
    const int n = blockIdx.x;
    const int tid = threadIdx.x;  // 192
    __shared__ float R[9], t3[3], qn_s[Hh], kn_s[Hh], pwb_s[Hh];
    const float* pr = d_proj + (size_t)n * PROJ_DIM;
    if (tid < 9)  R[tid] = rot[n * 9 + tid];
    if (tid < 3)  t3[tid] = trans[n * 3 + tid];
    if (tid < Hh) {
        qn_s[tid] = 0.f; kn_s[tid] = 0.f;
        float x = tpw[tid];
        float sp = (x > 20.f) ? x : log1pf(__expf(x));
        pwb_s[tid] = -0.5f * sp * POINT_W;
    }
    __syncthreads();

    { int h = tid >> 4, f = tid & 15;
      d_qcat[n * 384 + h * 32 + f] = SCALAR_W * pr[tid]; }
    for (int o = tid; o < 384; o += 192) {
        int h = o >> 5, d = o & 31;
        float v = pr[192 + o];
        if (d < 16) d_kT[(size_t)(h * 29 + d) * Nn + n] = v;
        else        d_vcat[(size_t)n * 480 + h * 16 + (d - 16)] = v;
    }
    if (tid < 48) {
        int m = tid;
        float p0 = pr[576 + 0 * 48 + m];
        float p1 = pr[576 + 1 * 48 + m];
        float p2 = pr[576 + 2 * 48 + m];
        float g0 = R[0] * p0 + R[1] * p1 + R[2] * p2 + t3[0];
        float g1 = R[3] * p0 + R[4] * p1 + R[5] * p2 + t3[1];
        float g2 = R[6] * p0 + R[7] * p1 + R[8] * p2 + t3[2];
        int h = m >> 2, p = m & 3;
        float s = -2.f * pwb_s[h];
        int base = n * 384 + h * 32 + 16 + p * 3;
        d_qcat[base + 0] = s * g0; d_qcat[base + 1] = s * g1; d_qcat[base + 2] = s * g2;
        atomicAdd(&qn_s[h], g0 * g0 + g1 * g1 + g2 * g2);
    } else {
        int m = tid - 48;
        float p0 = pr[720 + 0 * 144 + m];
        float p1 = pr[720 + 1 * 144 + m];
        float p2 = pr[720 + 2 * 144 + m];
        float g0 = R[0] * p0 + R[1] * p1 + R[2] * p2 + t3[0];
        float g1 = R[3] * p0 + R[4] * p1 + R[5] * p2 + t3[1];
        float g2 = R[6] * p0 + R[7] * p1 + R[8] * p2 + t3[2];
        int h = m / 12, pp = m % 12;
        if (pp < 4) {
            int fb = h * 29 + 16 + pp * 3;
            d_kT[(size_t)(fb + 0) * Nn + n] = g0;
            d_kT[(size_t)(fb + 1) * Nn + n] = g1;
            d_kT[(size_t)(fb + 2) * Nn + n] = g2;
            atomicAdd(&kn_s[h], g0 * g0 + g1 * g1 + g2 * g2);
        } else {
            int base = n * 480 + 192 + h * 24 + (pp - 4) * 3;
            d_vcat[base + 0] = g0; d_vcat[base + 1] = g1; d_vcat[base + 2] = g2;
        }
    }
    __syncthreads();
    if (tid < Hh) {
        int qb = n * 384 + tid * 32;
        d_qcat[qb + 28] = pwb_s[tid];
        d_qcat[qb + 29] = pwb_s[tid] * qn_s[tid] + W2D * b_a2[tid];
        d_qcat[qb + 30] = 0.f;
        d_qcat[qb + 31] = 0.f;
        d_kT[(size_t)(tid * 29 + 28) * Nn + n] = kn_s[tid];
    }
}

// ---------------- K3a: scalar/point/bias/mask logits as K=29 GEMM ----------------
// grid (12 jt, 12 it, 12 h), 128 threads
__global__ __launch_bounds__(128) void lgsp_kernel(const float* __restrict__ mask) {
    __shared__ float q_s[64][36];
    __shared__ float kt_s[29][68];
    __shared__ float mj_s[64];
    const int jt = blockIdx.x * 64;
    const int it = blockIdx.y * 64;
    const int h  = blockIdx.z;
    const int tid = threadIdx.x;

    for (int k = tid; k < 512; k += 128) {
        int r = k >> 3, c4 = k & 7;
        *(((float4*)&q_s[r][0]) + c4) =
            *(((const float4*)(d_qcat + (size_t)(it + r) * 384 + h * 32)) + c4);
    }
    for (int k = tid; k < 464; k += 128) {
        int f = k >> 4, c4 = k & 15;
        *(((float4*)&kt_s[f][0]) + c4) =
            *(((const float4*)(d_kT + (size_t)(h * 29 + f) * Nn + jt)) + c4);
    }
    if (tid < 64) mj_s[tid] = mask[jt + tid];
    __syncthreads();

    const int tj = tid & 7, ti = tid >> 3;
    float acc[4][8] = {};
#pragma unroll
    for (int f = 0; f < 29; f++) {
        float a[4], b[8];
#pragma unroll
        for (int r = 0; r < 4; r++) a[r] = q_s[ti * 4 + r][f];
#pragma unroll
        for (int c = 0; c < 8; c++) b[c] = kt_s[f][tj * 8 + c];
#pragma unroll
        for (int r = 0; r < 4; r++)
#pragma unroll
            for (int c = 0; c < 8; c++) acc[r][c] += a[r] * b[c];
    }
#pragma unroll
    for (int r = 0; r < 4; r++) {
        const int ii = it + ti * 4 + r;
        const float mi = mask[ii];
        const float cih = q_s[ti * 4 + r][29];
        float* orow = d_lgsp + ((size_t)ii * Hh + h) * Nn + jt + tj * 8;
#pragma unroll
        for (int c = 0; c < 8; c++)
            orow[c] = acc[r][c] + cih - 100000.f * (1.f - mi * mj_s[tj * 8 + c]);
    }
}

// ---------------- K3b: fused a2d GEMM + lgsp + softmax -> attn, attnT ----------------
// 768 blocks, 128 threads, dyn smem 67968 B
__global__ __launch_bounds__(128) void attn2_kernel(const float* __restrict__ in2d,
                                                    const float* __restrict__ w_a2) {
    extern __shared__ float sm[];
    float4* xs4 = (float4*)sm;                 // 15360 floats (768*5 float4)
    float4* ws4 = (float4*)(sm + 15360);       // 1584 floats (12*33 float4)
    float* red  = sm + 16944;                  // 48 floats
    float* att_s = sm;                         // alias (768*13 floats, used after compute)

    const int i = blockIdx.x;
    const int tid = threadIdx.x;
    const int wid = tid >> 5, lane = tid & 31;

    const float4* w4g = (const float4*)w_a2;
    for (int k = tid; k < 384; k += 128)
        ws4[(k >> 5) * 33 + (k & 31)] = w4g[k];

    float acc[12][6] = {};
    const float4* in4 = (const float4*)in2d + (size_t)i * Nn * 32;

    for (int cc = 0; cc < 8; cc++) {
        __syncthreads();
        for (int k = tid; k < 3072; k += 128) {
            int j = k >> 2, c4 = k & 3;
            xs4[j * 5 + c4] = in4[(size_t)j * 32 + cc * 4 + c4];
        }
        __syncthreads();
#pragma unroll
        for (int c4 = 0; c4 < 4; c4++) {
            float4 xv[6];
#pragma unroll
            for (int u = 0; u < 6; u++) xv[u] = xs4[(tid + 128 * u) * 5 + c4];
#pragma unroll
            for (int h = 0; h < 12; h++) {
                float4 wv = ws4[h * 33 + cc * 4 + c4];
#pragma unroll
                for (int u = 0; u < 6; u++)
                    acc[h][u] += xv[u].x * wv.x + xv[u].y * wv.y + xv[u].z * wv.z + xv[u].w * wv.w;
            }
        }
    }

    // add lgsp, per-head max
    const float* lgp = d_lgsp + (size_t)i * Hh * Nn;
#pragma unroll
    for (int h = 0; h < 12; h++) {
        float mx = -1e30f;
#pragma unroll
        for (int u = 0; u < 6; u++) {
            float L = acc[h][u] * W2D + lgp[h * Nn + tid + 128 * u];
            acc[h][u] = L;
            mx = fmaxf(mx, L);
        }
#pragma unroll
        for (int off = 16; off > 0; off >>= 1)
            mx = fmaxf(mx, __shfl_xor_sync(0xffffffffu, mx, off));
        if (lane == 0) red[wid * 12 + h] = mx;
    }
    __syncthreads();
    float mxh[12];
#pragma unroll
    for (int h = 0; h < 12; h++)
        mxh[h] = fmaxf(fmaxf(red[h], red[12 + h]), fmaxf(red[24 + h], red[36 + h]));
    __syncthreads();

#pragma unroll
    for (int h = 0; h < 12; h++) {
        float s = 0.f;
#pragma unroll
        for (int u = 0; u < 6; u++) {
            float e = __expf(acc[h][u] - mxh[h]);
            acc[h][u] = e;
            s += e;
        }
#pragma unroll
        for (int off = 16; off > 0; off >>= 1)
            s += __shfl_xor_sync(0xffffffffu, s, off);
        if (lane == 0) red[wid * 12 + h] = s;
    }
    __syncthreads();
    float smh[12];
#pragma unroll
    for (int h = 0; h < 12; h++)
        smh[h] = 1.f / (red[h] + red[12 + h] + red[24 + h] + red[36 + h]);
    __syncthreads();   // before att_s overwrites xs4 region

#pragma unroll
    for (int h = 0; h < 12; h++) {
        float* arow = d_attn + ((size_t)i * Hh + h) * Nn;
#pragma unroll
        for (int u = 0; u < 6; u++) {
            float a = acc[h][u] * smh[h];
            arow[tid + 128 * u] = a;
            att_s[(tid + 128 * u) * 13 + h] = a;
        }
    }
    __syncthreads();
    float4* oT = (float4*)(d_attnT + (size_t)i * (Nn * Hh));
    for (int k = tid; k < 2304; k += 128) {
        int j = k / 3, hq = (k % 3) * 4;
        float4 v;
        v.x = att_s[j * 13 + hq + 0];
        v.y = att_s[j * 13 + hq + 1];
        v.z = att_s[j * 13 + hq + 2];
        v.w = att_s[j * 13 + hq + 3];
        oT[k] = v;
    }
}

// ---------------- K5: r2d per-i GEMM attn[12,768] @ X[768,128] ----------------
// 768 blocks, 256 threads, dyn smem 86016 B
__global__ __launch_bounds__(256) void r2d_kernel(const float* __restrict__ in2d) {
    extern __shared__ float sm[];
    float* att_s = sm;            // 9216
    float* red   = sm + 9216;     // 12288
    const int i = blockIdx.x;
    const int tid = threadIdx.x;

    float4* as4 = (float4*)att_s;
    const float4* at4 = (const float4*)(d_attnT + (size_t)i * (Nn * Hh));
    for (int k = tid; k < 2304; k += 256) as4[k] = at4[k];
    __syncthreads();

    const int c4 = tid & 31, js = tid >> 5;  // js 0..7
    float acc[48] = {};
    const float4* x4p = (const float4*)in2d + (size_t)i * Nn * 32 + c4;
    const int jend = js * 96 + 96;
    for (int j = js * 96; j < jend; j++) {
        float4 x = x4p[(size_t)j * 32];
        float4 a0 = as4[j * 3 + 0], a1 = as4[j * 3 + 1], a2 = as4[j * 3 + 2];
        float a[12] = {a0.x, a0.y, a0.z, a0.w, a1.x, a1.y, a1.z, a1.w, a2.x, a2.y, a2.z, a2.w};
#pragma unroll
        for (int h = 0; h < 12; h++) {
            acc[h * 4 + 0] += a[h] * x.x;
            acc[h * 4 + 1] += a[h] * x.y;
            acc[h * 4 + 2] += a[h] * x.z;
            acc[h * 4 + 3] += a[h] * x.w;
        }
    }
#pragma unroll
    for (int k = 0; k < 48; k++) {
        int h = k >> 2, u = k & 3;
        red[js * 1536 + h * 128 + c4 * 4 + u] = acc[k];
    }
    __syncthreads();
    float* fa = d_fa + (size_t)i * FA_DIM + 576;
    for (int k = tid; k < 1536; k += 256) {
        float s = 0.f;
#pragma unroll
        for (int z = 0; z < 8; z++) s += red[z * 1536 + k];
        fa[k] = s;
    }
}

// ---------------- K6: PV tiled GEMM (result_scalar + rpg) ----------------
__global__ void pv_kernel() {
    __shared__ float att_s[64 * 33];
    __shared__ float v_s[32 * 40];
    const int i0 = blockIdx.x * 64;
    const int h = blockIdx.y;
    const int tid = threadIdx.x;
    const int io2 = tid & 31, ov = tid >> 5;
    float acc0[5] = {}, acc1[5] = {};

    for (int jt = 0; jt < Nn; jt += 32) {
        __syncthreads();
#pragma unroll
        for (int k = 0; k < 8; k++) {
            int f = tid + 256 * k;
            int il = f >> 5, jl = f & 31;
            att_s[il * 33 + jl] = d_attn[((size_t)(i0 + il) * 12 + h) * Nn + jt + jl];
        }
#pragma unroll
        for (int k = 0; k < 5; k++) {
            int f = tid + 256 * k;
            int jl = f / 40, o = f % 40;
            const float* vr = d_vcat + (size_t)(jt + jl) * 480;
            v_s[jl * 40 + o] = (o < 16) ? vr[h * 16 + o] : vr[192 + h * 24 + (o - 16)];
        }
        __syncthreads();
#pragma unroll 4
        for (int jl = 0; jl < 32; jl++) {
            float a0 = att_s[io2 * 33 + jl];
            float a1 = att_s[(io2 + 32) * 33 + jl];
#pragma unroll
            for (int u = 0; u < 5; u++) {
                float vv = v_s[jl * 40 + ov * 5 + u];
                acc0[u] += a0 * vv;
                acc1[u] += a1 * vv;
            }
        }
    }
#pragma unroll
    for (int u = 0; u < 5; u++) {
        int o = ov * 5 + u;
        int i_a = i0 + io2, i_b = i0 + io2 + 32;
        if (o < 16) {
            d_fa[(size_t)i_a * FA_DIM + h * 16 + o] = acc0[u];
            d_fa[(size_t)i_b * FA_DIM + h * 16 + o] = acc1[u];
        } else {
            d_rpg[i_a * 288 + h * 24 + (o - 16)] = acc0[u];
            d_rpg[i_b * 288 + h * 24 + (o - 16)] = acc1[u];
        }
    }
}

// ---------------- K7: local frame + dist ----------------
__global__ void local_kernel(const float* __restrict__ rot, const float* __restrict__ trans) {
    __shared__ float rpg_s[288], loc[288], Ri[9], ti[3];
    const int i = blockIdx.x;
    const int tid = threadIdx.x;  // 288
    rpg_s[tid] = d_rpg[i * 288 + tid];
    if (tid < 9) Ri[tid] = rot[i * 9 + tid];
    if (tid < 3) ti[tid] = trans[i * 3 + tid];
    __syncthreads();
    float* fa = d_fa + (size_t)i * FA_DIM;
    const int idim = tid / 96, m = tid % 96;
    const int hh = m >> 3, p = m & 7;
    const int base = hh * 24 + p * 3;
    float v0 = rpg_s[base + 0] - ti[0];
    float v1 = rpg_s[base + 1] - ti[1];
    float v2 = rpg_s[base + 2] - ti[2];
    float l = Ri[idim] * v0 + Ri[3 + idim] * v1 + Ri[6 + idim] * v2;
    loc[idim * 96 + m] = l;
    fa[192 + idim * 96 + m] = l;
    __syncthreads();
    if (tid < 96) {
        float l0 = loc[tid], l1 = loc[96 + tid], l2 = loc[192 + tid];
        fa[480 + tid] = sqrtf(1e-8f + l0 * l0 + l1 * l1 + l2 * l2);
    }
}

// ---------------- K8: reduce out partials + bias ----------------
__global__ void reduce_out_kernel(const float* __restrict__ b_out, float* __restrict__ out) {
    const int idx = blockIdx.x * 256 + threadIdx.x;
    const int total = Nn * 384;
    if (idx < total) {
        out[idx] = b_out[idx % 384] + d_part[idx] + d_part[total + idx]
                 + d_part[2 * total + idx] + d_part[3 * total + idx];
    }
}

// ---------------- launch ----------------
extern "C" void kernel_launch(void* const* d_in, const int* in_sizes, int n_in,
                              void* d_out, int out_size) {
    const float* inputs_1d = (const float*)d_in[0];
    const float* inputs_2d = (const float*)d_in[1];
    const float* mask      = (const float*)d_in[2];
    const float* rotation  = (const float*)d_in[3];
    const float* translat  = (const float*)d_in[4];
    const float* w_qs      = (const float*)d_in[5];
    const float* b_qs      = (const float*)d_in[6];
    const float* w_kvs     = (const float*)d_in[7];
    const float* b_kvs     = (const float*)d_in[8];
    const float* w_qp      = (const float*)d_in[9];
    const float* b_qp      = (const float*)d_in[10];
    const float* w_kvp     = (const float*)d_in[11];
    const float* b_kvp     = (const float*)d_in[12];
    const float* tpw       = (const float*)d_in[13];
    const float* w_a2      = (const float*)d_in[14];
    const float* b_a2      = (const float*)d_in[15];
    const float* w_out     = (const float*)d_in[16];
    const float* b_out     = (const float*)d_in[17];
    float* out = (float*)d_out;

    void *p_wcat, *p_bcat, *p_proj;
    cudaGetSymbolAddress(&p_wcat, d_wcat);
    cudaGetSymbolAddress(&p_bcat, d_bcat);
    cudaGetSymbolAddress(&p_proj, d_proj);

    concat_w_kernel<<<256, 256>>>(w_qs, w_kvs, w_qp, w_kvp, b_qs, b_kvs, b_qp, b_kvp);

    {
        dim3 grid(PROJ_DIM / 64, Nn / 64);
        gemm_tn2<<<grid, 256>>>(inputs_1d, C1d, (const float*)p_wcat, C1d,
                                (const float*)p_bcat, (float*)p_proj, C1d, PROJ_DIM);
    }

    rot_kernel<<<Nn, 192>>>(rotation, translat, tpw, b_a2);

    lgsp_kernel<<<dim3(12, 12, 12), 128>>>(mask);

    {
        const int smem = 16992 * (int)sizeof(float);
        cudaFuncSetAttribute(attn2_kernel, cudaFuncAttributeMaxDynamicSharedMemorySize, smem);
        attn2_kernel<<<Nn, 128, smem>>>(inputs_2d, w_a2);
    }

    {
        const int smem = (9216 + 12288) * (int)sizeof(float);
        cudaFuncSetAttribute(r2d_kernel, cudaFuncAttributeMaxDynamicSharedMemorySize, smem);
        r2d_kernel<<<Nn, 256, smem>>>(inputs_2d);
    }

    pv_kernel<<<dim3(Nn / 64, Hh), 256>>>();
    local_kernel<<<Nn, 288>>>(rotation, translat);

    gemm_out_kernel<<<dim3(6, 12, 4), 256>>>(w_out);
    reduce_out_kernel<<<(Nn * 384 + 255) / 256, 256>>>(b_out, out);
}

// round 5
// speedup vs baseline: 3.5433x; 1.0497x over previous
#include <cuda_runtime.h>
#include <math.h>
#include <stdint.h>

#define Hh   12
#define Nn   768
#define C1d  384
#define C2d  128
#define PROJ_DIM 1152
#define FA_DIM   2112

#define SCALAR_W 0.14433756729740643f
#define POINT_W  0.13608276348795434f
#define W2D      0.5773502691896258f

// ---------------- scratch ----------------
__device__ float d_wcat[PROJ_DIM * C1d];
__device__ float d_bcat[PROJ_DIM];
__device__ float d_proj[Nn * PROJ_DIM];
__device__ float d_qcat[Nn * 384];        // [i][h*32+f]
__device__ float d_kT[Hh * 29 * Nn];      // [h][f][j]
__device__ float d_vcat[Nn * 480];        // [j][480]
__device__ float d_lgsp[Nn * Hh * Nn];    // [i][h][j]
__device__ float d_attn[Hh * Nn * Nn];    // [i][h][j]
__device__ float d_rpg[Nn * 288];
__device__ float d_fa[Nn * FA_DIM];
__device__ float d_part[4 * Nn * 384];

// ---------------- K0: concat proj weights ----------------
__global__ void concat_w_kernel(const float* __restrict__ wqs, const float* __restrict__ wkvs,
                                const float* __restrict__ wqp, const float* __restrict__ wkvp,
                                const float* __restrict__ bqs, const float* __restrict__ bkvs,
                                const float* __restrict__ bqp, const float* __restrict__ bkvp) {
    int idx = blockIdx.x * blockDim.x + threadIdx.x;
    int stride = gridDim.x * blockDim.x;
    for (int o = idx; o < PROJ_DIM; o += stride) {
        float v;
        if (o < 192)      v = bqs[o];
        else if (o < 576) v = bkvs[o - 192];
        else if (o < 720) v = bqp[o - 576];
        else              v = bkvp[o - 720];
        d_bcat[o] = v;
    }
    const int total = PROJ_DIM * C1d;
    for (int t = idx; t < total; t += stride) {
        int o = t / C1d, k = t % C1d;
        float v;
        if (o < 192)      v = wqs[o * C1d + k];
        else if (o < 576) v = wkvs[(o - 192) * C1d + k];
        else if (o < 720) v = wqp[(o - 576) * C1d + k];
        else              v = wkvp[(o - 720) * C1d + k];
        d_wcat[t] = v;
    }
}

// ---------------- generic fp32 GEMM ----------------
__global__ void gemm_tn2(const float* __restrict__ X, int ldx,
                         const float* __restrict__ W, int ldw,
                         const float* __restrict__ bias, float* __restrict__ C,
                         int Klen, int O) {
    __shared__ float xs[64][17];
    __shared__ float wsh[64][17];
    const int m0 = blockIdx.y * 64;
    const int o0 = blockIdx.x * 64;
    const int tx = threadIdx.x;
    const int tm = (tx & 15) * 4;
    const int to = (tx >> 4) * 4;
    float acc[4][4] = {};
    for (int k0 = 0; k0 < Klen; k0 += 16) {
        for (int idx = tx; idx < 64 * 16; idx += 256) {
            int r = idx >> 4, c = idx & 15;
            xs[r][c]  = X[(size_t)(m0 + r) * ldx + k0 + c];
            wsh[r][c] = W[(size_t)(o0 + r) * ldw + k0 + c];
        }
        __syncthreads();
#pragma unroll
        for (int k = 0; k < 16; k++) {
            float a[4], b[4];
#pragma unroll
            for (int i = 0; i < 4; i++) { a[i] = xs[tm + i][k]; b[i] = wsh[to + i][k]; }
#pragma unroll
            for (int i = 0; i < 4; i++)
#pragma unroll
                for (int j = 0; j < 4; j++) acc[i][j] += a[i] * b[j];
        }
        __syncthreads();
    }
#pragma unroll
    for (int i = 0; i < 4; i++)
#pragma unroll
        for (int j = 0; j < 4; j++) {
            float b = bias ? bias[o0 + to + j] : 0.f;
            C[(size_t)(m0 + tm + i) * O + o0 + to + j] = acc[i][j] + b;
        }
}

// ---------------- out-GEMM, K-split on z ----------------
__global__ void gemm_out_kernel(const float* __restrict__ Wo) {
    __shared__ float xs[64][17];
    __shared__ float wsh[64][17];
    const int z  = blockIdx.z;
    const float* X = d_fa + z * 528;
    const float* W = Wo + z * 528;
    float* C = d_part + (size_t)z * (Nn * 384);
    const int m0 = blockIdx.y * 64;
    const int o0 = blockIdx.x * 64;
    const int tx = threadIdx.x;
    const int tm = (tx & 15) * 4;
    const int to = (tx >> 4) * 4;
    float acc[4][4] = {};
    for (int k0 = 0; k0 < 528; k0 += 16) {
        for (int idx = tx; idx < 64 * 16; idx += 256) {
            int r = idx >> 4, c = idx & 15;
            xs[r][c]  = X[(size_t)(m0 + r) * FA_DIM + k0 + c];
            wsh[r][c] = W[(size_t)(o0 + r) * FA_DIM + k0 + c];
        }
        __syncthreads();
#pragma unroll
        for (int k = 0; k < 16; k++) {
            float a[4], b[4];
#pragma unroll
            for (int i = 0; i < 4; i++) { a[i] = xs[tm + i][k]; b[i] = wsh[to + i][k]; }
#pragma unroll
            for (int i = 0; i < 4; i++)
#pragma unroll
                for (int j = 0; j < 4; j++) acc[i][j] += a[i] * b[j];
        }
        __syncthreads();
    }
#pragma unroll
    for (int i = 0; i < 4; i++)
#pragma unroll
        for (int j = 0; j < 4; j++)
            C[(size_t)(m0 + tm + i) * 384 + o0 + to + j] = acc[i][j];
}

// ---------------- K2: rotations / frames / norms / packed q ----------------
__global__ void rot_kernel(const float* __restrict__ rot, const float* __restrict__ trans,
                           const float* __restrict__ tpw, const float* __restrict__ b_a2) {
    const int n = blockIdx.x;
    const int tid = threadIdx.x;  // 192
    __shared__ float R[9], t3[3], qn_s[Hh], kn_s[Hh], pwb_s[Hh];
    const float* pr = d_proj + (size_t)n * PROJ_DIM;
    if (tid < 9)  R[tid] = rot[n * 9 + tid];
    if (tid < 3)  t3[tid] = trans[n * 3 + tid];
    if (tid < Hh) {
        qn_s[tid] = 0.f; kn_s[tid] = 0.f;
        float x = tpw[tid];
        float sp = (x > 20.f) ? x : log1pf(__expf(x));
        pwb_s[tid] = -0.5f * sp * POINT_W;
    }
    __syncthreads();

    { int h = tid >> 4, f = tid & 15;
      d_qcat[n * 384 + h * 32 + f] = SCALAR_W * pr[tid]; }
    for (int o = tid; o < 384; o += 192) {
        int h = o >> 5, d = o & 31;
        float v = pr[192 + o];
        if (d < 16) d_kT[(size_t)(h * 29 + d) * Nn + n] = v;
        else        d_vcat[(size_t)n * 480 + h * 16 + (d - 16)] = v;
    }
    if (tid < 48) {
        int m = tid;
        float p0 = pr[576 + 0 * 48 + m];
        float p1 = pr[576 + 1 * 48 + m];
        float p2 = pr[576 + 2 * 48 + m];
        float g0 = R[0] * p0 + R[1] * p1 + R[2] * p2 + t3[0];
        float g1 = R[3] * p0 + R[4] * p1 + R[5] * p2 + t3[1];
        float g2 = R[6] * p0 + R[7] * p1 + R[8] * p2 + t3[2];
        int h = m >> 2, p = m & 3;
        float s = -2.f * pwb_s[h];
        int base = n * 384 + h * 32 + 16 + p * 3;
        d_qcat[base + 0] = s * g0; d_qcat[base + 1] = s * g1; d_qcat[base + 2] = s * g2;
        atomicAdd(&qn_s[h], g0 * g0 + g1 * g1 + g2 * g2);
    } else {
        int m = tid - 48;
        float p0 = pr[720 + 0 * 144 + m];
        float p1 = pr[720 + 1 * 144 + m];
        float p2 = pr[720 + 2 * 144 + m];
        float g0 = R[0] * p0 + R[1] * p1 + R[2] * p2 + t3[0];
        float g1 = R[3] * p0 + R[4] * p1 + R[5] * p2 + t3[1];
        float g2 = R[6] * p0 + R[7] * p1 + R[8] * p2 + t3[2];
        int h = m / 12, pp = m % 12;
        if (pp < 4) {
            int fb = h * 29 + 16 + pp * 3;
            d_kT[(size_t)(fb + 0) * Nn + n] = g0;
            d_kT[(size_t)(fb + 1) * Nn + n] = g1;
            d_kT[(size_t)(fb + 2) * Nn + n] = g2;
            atomicAdd(&kn_s[h], g0 * g0 + g1 * g1 + g2 * g2);
        } else {
            int base = n * 480 + 192 + h * 24 + (pp - 4) * 3;
            d_vcat[base + 0] = g0; d_vcat[base + 1] = g1; d_vcat[base + 2] = g2;
        }
    }
    __syncthreads();
    if (tid < Hh) {
        int qb = n * 384 + tid * 32;
        d_qcat[qb + 28] = pwb_s[tid];
        d_qcat[qb + 29] = pwb_s[tid] * qn_s[tid] + W2D * b_a2[tid];
        d_qcat[qb + 30] = 0.f;
        d_qcat[qb + 31] = 0.f;
        d_kT[(size_t)(tid * 29 + 28) * Nn + n] = kn_s[tid];
    }
}

// ---------------- K3a: scalar/point logits, K=29 GEMM, 8x8 register tile ----------------
// grid (6 jt, 12 it, 12 h), 128 threads; tile 64 i x 128 j
__global__ __launch_bounds__(128) void lgsp_kernel(const float* __restrict__ mask) {
    __shared__ float q_s[64][36];
    __shared__ float kt_s[29][132];
    __shared__ float mj_s[128];
    const int jt = blockIdx.x * 128;
    const int it = blockIdx.y * 64;
    const int h  = blockIdx.z;
    const int tid = threadIdx.x;

    for (int k = tid; k < 512; k += 128) {
        int r = k >> 3, c4 = k & 7;
        *(((float4*)&q_s[r][0]) + c4) =
            *(((const float4*)(d_qcat + (size_t)(it + r) * 384 + h * 32)) + c4);
    }
    for (int k = tid; k < 928; k += 128) {
        int f = k >> 5, c4 = k & 31;
        *(((float4*)&kt_s[f][0]) + c4) =
            *(((const float4*)(d_kT + (size_t)(h * 29 + f) * Nn + jt)) + c4);
    }
    if (tid < 128) mj_s[tid] = mask[jt + tid];
    __syncthreads();

    const int tj = tid & 15, ti = tid >> 4;  // 16 j-groups x 8 i-groups
    float acc[8][8] = {};
#pragma unroll
    for (int f = 0; f < 29; f++) {
        float a[8];
        float4 b0 = *((const float4*)&kt_s[f][tj * 8]);
        float4 b1 = *((const float4*)&kt_s[f][tj * 8 + 4]);
        float b[8] = {b0.x, b0.y, b0.z, b0.w, b1.x, b1.y, b1.z, b1.w};
#pragma unroll
        for (int r = 0; r < 8; r++) a[r] = q_s[ti * 8 + r][f];
#pragma unroll
        for (int r = 0; r < 8; r++)
#pragma unroll
            for (int c = 0; c < 8; c++) acc[r][c] += a[r] * b[c];
    }
#pragma unroll
    for (int r = 0; r < 8; r++) {
        const int ii = it + ti * 8 + r;
        const float mi = mask[ii];
        const float cih = q_s[ti * 8 + r][29];
        float4* orow = (float4*)(d_lgsp + ((size_t)ii * Hh + h) * Nn + jt + tj * 8);
        float4 o0, o1;
        o0.x = acc[r][0] + cih - 100000.f * (1.f - mi * mj_s[tj * 8 + 0]);
        o0.y = acc[r][1] + cih - 100000.f * (1.f - mi * mj_s[tj * 8 + 1]);
        o0.z = acc[r][2] + cih - 100000.f * (1.f - mi * mj_s[tj * 8 + 2]);
        o0.w = acc[r][3] + cih - 100000.f * (1.f - mi * mj_s[tj * 8 + 3]);
        o1.x = acc[r][4] + cih - 100000.f * (1.f - mi * mj_s[tj * 8 + 4]);
        o1.y = acc[r][5] + cih - 100000.f * (1.f - mi * mj_s[tj * 8 + 5]);
        o1.z = acc[r][6] + cih - 100000.f * (1.f - mi * mj_s[tj * 8 + 6]);
        o1.w = acc[r][7] + cih - 100000.f * (1.f - mi * mj_s[tj * 8 + 7]);
        orow[0] = o0; orow[1] = o1;
    }
}

// ---------------- K3b: fused a2d GEMM + lgsp + softmax + r2d ----------------
// 768 blocks, 256 threads, dyn smem 105024 B
__global__ __launch_bounds__(256) void attn_fused_kernel(const float* __restrict__ in2d,
                                                         const float* __restrict__ w_a2) {
    extern __shared__ float sm[];
    float4* xs4 = (float4*)sm;                 // 15360 floats (768*5 f4); reused as red-buf
    float4* ws4 = (float4*)(sm + 15360);       // 1584 floats
    float* att_s = sm + 16944;                 // 9216 floats
    float* red   = sm + 26160;                 // 96 floats

    const int i = blockIdx.x;
    const int tid = threadIdx.x;
    const int wid = tid >> 5, lane = tid & 31;

    const float4* w4g = (const float4*)w_a2;
    for (int k = tid; k < 384; k += 256)
        ws4[(k >> 5) * 33 + (k & 31)] = w4g[k];

    float acc[12][3] = {};
    const float4* in4 = (const float4*)in2d + (size_t)i * Nn * 32;

    // ---- phase A: a2d GEMM ----
    for (int cc = 0; cc < 8; cc++) {
        __syncthreads();
        for (int k = tid; k < 3072; k += 256) {
            int j = k >> 2, c4 = k & 3;
            xs4[j * 5 + c4] = in4[(size_t)j * 32 + cc * 4 + c4];
        }
        __syncthreads();
#pragma unroll
        for (int c4 = 0; c4 < 4; c4++) {
            float4 xv[3];
#pragma unroll
            for (int u = 0; u < 3; u++) xv[u] = xs4[(tid + 256 * u) * 5 + c4];
#pragma unroll
            for (int h = 0; h < 12; h++) {
                float4 wv = ws4[h * 33 + cc * 4 + c4];
#pragma unroll
                for (int u = 0; u < 3; u++)
                    acc[h][u] += xv[u].x * wv.x + xv[u].y * wv.y + xv[u].z * wv.z + xv[u].w * wv.w;
            }
        }
    }

    // ---- phase B: + lgsp, softmax ----
    const float* lgp = d_lgsp + (size_t)i * Hh * Nn;
#pragma unroll
    for (int h = 0; h < 12; h++) {
        float mx = -1e30f;
#pragma unroll
        for (int u = 0; u < 3; u++) {
            float L = acc[h][u] * W2D + lgp[h * Nn + tid + 256 * u];
            acc[h][u] = L;
            mx = fmaxf(mx, L);
        }
#pragma unroll
        for (int off = 16; off > 0; off >>= 1)
            mx = fmaxf(mx, __shfl_xor_sync(0xffffffffu, mx, off));
        if (lane == 0) red[wid * 12 + h] = mx;
    }
    __syncthreads();
    float mxh[12];
#pragma unroll
    for (int h = 0; h < 12; h++) {
        float m = red[h];
#pragma unroll
        for (int w = 1; w < 8; w++) m = fmaxf(m, red[w * 12 + h]);
        mxh[h] = m;
    }
    __syncthreads();

#pragma unroll
    for (int h = 0; h < 12; h++) {
        float s = 0.f;
#pragma unroll
        for (int u = 0; u < 3; u++) {
            float e = __expf(acc[h][u] - mxh[h]);
            acc[h][u] = e;
            s += e;
        }
#pragma unroll
        for (int off = 16; off > 0; off >>= 1)
            s += __shfl_xor_sync(0xffffffffu, s, off);
        if (lane == 0) red[wid * 12 + h] = s;
    }
    __syncthreads();
    float smh[12];
#pragma unroll
    for (int h = 0; h < 12; h++) {
        float s = 0.f;
#pragma unroll
        for (int w = 0; w < 8; w++) s += red[w * 12 + h];
        smh[h] = 1.f / s;
    }

#pragma unroll
    for (int h = 0; h < 12; h++) {
        float* arow = d_attn + ((size_t)i * Hh + h) * Nn;
#pragma unroll
        for (int u = 0; u < 3; u++) {
            float a = acc[h][u] * smh[h];
            int j = tid + 256 * u;
            arow[j] = a;
            att_s[j * 12 + h] = a;
        }
    }
    __syncthreads();

    // ---- phase C: r2d = attn[12,768] @ X[768,128] ----
    {
        const float4* as4 = (const float4*)att_s;
        const int c4 = tid & 31, js = tid >> 5;  // 8 j-slices of 96
        float r2[48] = {};
        const float4* x4p = in4 + c4;
        const int jbeg = js * 96;
        for (int j = jbeg; j < jbeg + 96; j += 2) {
            float4 xa = x4p[(size_t)j * 32];
            float4 xb = x4p[(size_t)(j + 1) * 32];
            float4 a0 = as4[j * 3 + 0], a1 = as4[j * 3 + 1], a2 = as4[j * 3 + 2];
            float4 b0 = as4[j * 3 + 3], b1 = as4[j * 3 + 4], b2 = as4[j * 3 + 5];
            float aa[12] = {a0.x, a0.y, a0.z, a0.w, a1.x, a1.y, a1.z, a1.w, a2.x, a2.y, a2.z, a2.w};
            float bb[12] = {b0.x, b0.y, b0.z, b0.w, b1.x, b1.y, b1.z, b1.w, b2.x, b2.y, b2.z, b2.w};
#pragma unroll
            for (int h = 0; h < 12; h++) {
                r2[h * 4 + 0] += aa[h] * xa.x + bb[h] * xb.x;
                r2[h * 4 + 1] += aa[h] * xa.y + bb[h] * xb.y;
                r2[h * 4 + 2] += aa[h] * xa.z + bb[h] * xb.z;
                r2[h * 4 + 3] += aa[h] * xa.w + bb[h] * xb.w;
            }
        }
        __syncthreads();  // xs4 free now
        float* redc = sm;
#pragma unroll
        for (int k = 0; k < 48; k++) {
            int h = k >> 2, u = k & 3;
            redc[js * 1536 + h * 128 + c4 * 4 + u] = r2[k];
        }
        __syncthreads();
        float* fa = d_fa + (size_t)i * FA_DIM + 576;
        for (int k = tid; k < 1536; k += 256) {
            float s = 0.f;
#pragma unroll
            for (int z = 0; z < 8; z++) s += redc[z * 1536 + k];
            fa[k] = s;
        }
    }
}

// ---------------- K6: PV tiled GEMM ----------------
__global__ void pv_kernel() {
    __shared__ float att_s[64 * 33];
    __shared__ float v_s[32 * 40];
    const int i0 = blockIdx.x * 64;
    const int h = blockIdx.y;
    const int tid = threadIdx.x;
    const int io2 = tid & 31, ov = tid >> 5;
    float acc0[5] = {}, acc1[5] = {};

    for (int jt = 0; jt < Nn; jt += 32) {
        __syncthreads();
#pragma unroll
        for (int k = 0; k < 8; k++) {
            int f = tid + 256 * k;
            int il = f >> 5, jl = f & 31;
            att_s[il * 33 + jl] = d_attn[((size_t)(i0 + il) * 12 + h) * Nn + jt + jl];
        }
#pragma unroll
        for (int k = 0; k < 5; k++) {
            int f = tid + 256 * k;
            int jl = f / 40, o = f % 40;
            const float* vr = d_vcat + (size_t)(jt + jl) * 480;
            v_s[jl * 40 + o] = (o < 16) ? vr[h * 16 + o] : vr[192 + h * 24 + (o - 16)];
        }
        __syncthreads();
#pragma unroll 4
        for (int jl = 0; jl < 32; jl++) {
            float a0 = att_s[io2 * 33 + jl];
            float a1 = att_s[(io2 + 32) * 33 + jl];
#pragma unroll
            for (int u = 0; u < 5; u++) {
                float vv = v_s[jl * 40 + ov * 5 + u];
                acc0[u] += a0 * vv;
                acc1[u] += a1 * vv;
            }
        }
    }
#pragma unroll
    for (int u = 0; u < 5; u++) {
        int o = ov * 5 + u;
        int i_a = i0 + io2, i_b = i0 + io2 + 32;
        if (o < 16) {
            d_fa[(size_t)i_a * FA_DIM + h * 16 + o] = acc0[u];
            d_fa[(size_t)i_b * FA_DIM + h * 16 + o] = acc1[u];
        } else {
            d_rpg[i_a * 288 + h * 24 + (o - 16)] = acc0[u];
            d_rpg[i_b * 288 + h * 24 + (o - 16)] = acc1[u];
        }
    }
}

// ---------------- K7: local frame + dist ----------------
__global__ void local_kernel(const float* __restrict__ rot, const float* __restrict__ trans) {
    __shared__ float rpg_s[288], loc[288], Ri[9], ti[3];
    const int i = blockIdx.x;
    const int tid = threadIdx.x;  // 288
    rpg_s[tid] = d_rpg[i * 288 + tid];
    if (tid < 9) Ri[tid] = rot[i * 9 + tid];
    if (tid < 3) ti[tid] = trans[i * 3 + tid];
    __syncthreads();
    float* fa = d_fa + (size_t)i * FA_DIM;
    const int idim = tid / 96, m = tid % 96;
    const int hh = m >> 3, p = m & 7;
    const int base = hh * 24 + p * 3;
    float v0 = rpg_s[base + 0] - ti[0];
    float v1 = rpg_s[base + 1] - ti[1];
    float v2 = rpg_s[base + 2] - ti[2];
    float l = Ri[idim] * v0 + Ri[3 + idim] * v1 + Ri[6 + idim] * v2;
    loc[idim * 96 + m] = l;
    fa[192 + idim * 96 + m] = l;
    __syncthreads();
    if (tid < 96) {
        float l0 = loc[tid], l1 = loc[96 + tid], l2 = loc[192 + tid];
        fa[480 + tid] = sqrtf(1e-8f + l0 * l0 + l1 * l1 + l2 * l2);
    }
}

// ---------------- K8: reduce out partials + bias ----------------
__global__ void reduce_out_kernel(const float* __restrict__ b_out, float* __restrict__ out) {
    const int idx = blockIdx.x * 256 + threadIdx.x;
    const int total = Nn * 384;
    if (idx < total) {
        out[idx] = b_out[idx % 384] + d_part[idx] + d_part[total + idx]
                 + d_part[2 * total + idx] + d_part[3 * total + idx];
    }
}

// ---------------- launch ----------------
extern "C" void kernel_launch(void* const* d_in, const int* in_sizes, int n_in,
                              void* d_out, int out_size) {
    const float* inputs_1d = (const float*)d_in[0];
    const float* inputs_2d = (const float*)d_in[1];
    const float* mask      = (const float*)d_in[2];
    const float* rotation  = (const float*)d_in[3];
    const float* translat  = (const float*)d_in[4];
    const float* w_qs      = (const float*)d_in[5];
    const float* b_qs      = (const float*)d_in[6];
    const float* w_kvs     = (const float*)d_in[7];
    const float* b_kvs     = (const float*)d_in[8];
    const float* w_qp      = (const float*)d_in[9];
    const float* b_qp      = (const float*)d_in[10];
    const float* w_kvp     = (const float*)d_in[11];
    const float* b_kvp     = (const float*)d_in[12];
    const float* tpw       = (const float*)d_in[13];
    const float* w_a2      = (const float*)d_in[14];
    const float* b_a2      = (const float*)d_in[15];
    const float* w_out     = (const float*)d_in[16];
    const float* b_out     = (const float*)d_in[17];
    float* out = (float*)d_out;

    void *p_wcat, *p_bcat, *p_proj;
    cudaGetSymbolAddress(&p_wcat, d_wcat);
    cudaGetSymbolAddress(&p_bcat, d_bcat);
    cudaGetSymbolAddress(&p_proj, d_proj);

    concat_w_kernel<<<256, 256>>>(w_qs, w_kvs, w_qp, w_kvp, b_qs, b_kvs, b_qp, b_kvp);

    {
        dim3 grid(PROJ_DIM / 64, Nn / 64);
        gemm_tn2<<<grid, 256>>>(inputs_1d, C1d, (const float*)p_wcat, C1d,
                                (const float*)p_bcat, (float*)p_proj, C1d, PROJ_DIM);
    }

    rot_kernel<<<Nn, 192>>>(rotation, translat, tpw, b_a2);

    lgsp_kernel<<<dim3(6, 12, 12), 128>>>(mask);

    {
        const int smem = 26256 * (int)sizeof(float);
        cudaFuncSetAttribute(attn_fused_kernel, cudaFuncAttributeMaxDynamicSharedMemorySize, smem);
        attn_fused_kernel<<<Nn, 256, smem>>>(inputs_2d, w_a2);
    }

    pv_kernel<<<dim3(Nn / 64, Hh), 256>>>();
    local_kernel<<<Nn, 288>>>(rotation, translat);

    gemm_out_kernel<<<dim3(6, 12, 4), 256>>>(w_out);
    reduce_out_kernel<<<(Nn * 384 + 255) / 256, 256>>>(b_out, out);
}